// round 13
// baseline (speedup 1.0000x reference)
#include <cuda_runtime.h>
#include <cuda_fp16.h>
#include <cstdint>
#include <cstddef>

// Problem constants
#define DD 1024
#define MROWS 8192

// ---------------------------------------------------------------------------
// Device scratch (allocation-free rule: __device__ globals)
// ---------------------------------------------------------------------------
__device__ unsigned short g_xh[MROWS * DD];   // x as fp16 (16MB)
__device__ unsigned short g_wt[DD * DD];      // WT = (2048*Wv@Wo)^T as fp16
__device__ float g_bpart[8 * DD];             // bias j-group partials

// ---------------------------------------------------------------------------
// asm helpers (arch-neutral: mma.sync / ldmatrix / cp.async;
// tcgen05 unusable — harness PTX target is sm_103, not sm_103a)
// ---------------------------------------------------------------------------
__device__ __forceinline__ uint32_t smem_u32(const void* p) {
    uint32_t a;
    asm("{ .reg .u64 t; cvta.to.shared.u64 t, %1; cvt.u32.u64 %0, t; }" : "=r"(a) : "l"(p));
    return a;
}
#define CP16(dst, src) \
    asm volatile("cp.async.cg.shared.global [%0], [%1], 16;" :: "r"(dst), "l"(src))
#define CP_COMMIT()  asm volatile("cp.async.commit_group;" ::: "memory")
#define CP_WAIT1()   asm volatile("cp.async.wait_group 1;" ::: "memory")
#define CP_WAIT0()   asm volatile("cp.async.wait_group 0;" ::: "memory")

__device__ __forceinline__ void ldsm4(uint32_t& r0, uint32_t& r1, uint32_t& r2, uint32_t& r3,
                                      uint32_t addr) {
    asm volatile("ldmatrix.sync.aligned.m8n8.x4.shared.b16 {%0,%1,%2,%3}, [%4];"
                 : "=r"(r0), "=r"(r1), "=r"(r2), "=r"(r3) : "r"(addr));
}
__device__ __forceinline__ void mma_f16(float c[4], const uint32_t a[4], const uint32_t b[2]) {
    asm volatile(
        "mma.sync.aligned.m16n8k16.row.col.f32.f16.f16.f32 "
        "{%0,%1,%2,%3},{%4,%5,%6,%7},{%8,%9},{%0,%1,%2,%3};"
        : "+f"(c[0]), "+f"(c[1]), "+f"(c[2]), "+f"(c[3])
        : "r"(a[0]), "r"(a[1]), "r"(a[2]), "r"(a[3]), "r"(b[0]), "r"(b[1]));
}
__device__ __forceinline__ uint32_t pack_f16x2(float v0, float v1) {
    uint32_t r;
    asm("cvt.rn.f16x2.f32 %0, %1, %2;" : "=r"(r) : "f"(v1), "f"(v0));
    return r;
}
__device__ __forceinline__ unsigned short f2h(float v) {
    return (unsigned short)(pack_f16x2(v, 0.f) & 0xffffu);
}

// ---------------------------------------------------------------------------
// Fused stage-1 kernel (one launch, blocks partitioned by role):
//   [0,128):      W-GEMM tiles with INLINE fp32->fp16 operand conversion:
//                 WT[n][k] = 2048 * sum_j Wo[j][n] * Wv[k][j]  -> fp16
//   [128,2176):   x -> fp16 (2048 converter blocks)
//   [2176,2432):  bias partials bpart[g][n] = sum_{j in g} bv[j]*Wo[j][n]
// ---------------------------------------------------------------------------
#define S1_TILE_BLKS 128
#define S1_X_BLKS    2048
#define S1_B_BLKS    256
#define S1_BLKS (S1_TILE_BLKS + S1_X_BLKS + S1_B_BLKS)
// W-tile smem: 2 stages x (A 64x128B + B 128x128B) = 2 x 24576
#define S1_STAGE 24576
#define S1_SMEM  (2 * S1_STAGE)   // 49152

__global__ __launch_bounds__(256, 2)
void stage1_kernel(const float* __restrict__ Wo,   // [j][n] fp32
                   const float* __restrict__ Wv,   // [k][j] fp32
                   const float* __restrict__ bv,
                   unsigned short* __restrict__ wt, // WT out fp16 [n][k]... row n, k? see epilogue
                   const float4* __restrict__ x,
                   uint2* __restrict__ xh,
                   float* __restrict__ bpart) {
    extern __shared__ char smv[];
    const int bid = blockIdx.x;
    const int tid = threadIdx.x;

    if (bid >= S1_TILE_BLKS && bid < S1_TILE_BLKS + S1_X_BLKS) {
        // ---- x -> fp16 converter role
        int base = (bid - S1_TILE_BLKS) * 1024 + tid;
        float4 v0 = x[base];
        float4 v1 = x[base + 256];
        float4 v2 = x[base + 512];
        float4 v3 = x[base + 768];
        uint2 o0 = { pack_f16x2(v0.x, v0.y), pack_f16x2(v0.z, v0.w) };
        uint2 o1 = { pack_f16x2(v1.x, v1.y), pack_f16x2(v1.z, v1.w) };
        uint2 o2 = { pack_f16x2(v2.x, v2.y), pack_f16x2(v2.z, v2.w) };
        uint2 o3 = { pack_f16x2(v3.x, v3.y), pack_f16x2(v3.z, v3.w) };
        xh[base]       = o0;
        xh[base + 256] = o1;
        xh[base + 512] = o2;
        xh[base + 768] = o3;
        return;
    }
    if (bid >= S1_TILE_BLKS + S1_X_BLKS) {
        // ---- bias partials: 256 blocks = 8 j-groups x 32 n-blocks
        __shared__ float part[8][32];
        const int local = bid - (S1_TILE_BLKS + S1_X_BLKS);
        const int jg = local >> 5;           // 0..7
        const int n0 = (local & 31) * 32;
        const int nl = tid & 31;
        const int sj = tid >> 5;             // 0..7
        const int j0 = jg * 128 + sj * 16;
        float s = 0.f;
        #pragma unroll
        for (int j = 0; j < 16; j++)
            s += bv[j0 + j] * Wo[(size_t)(j0 + j) * DD + n0 + nl];
        part[sj][nl] = s;
        __syncthreads();
        if (tid < 32) {
            float acc = 0.f;
            #pragma unroll
            for (int g = 0; g < 8; g++) acc += part[g][nl];
            bpart[jg * DD + n0 + nl] = acc;
        }
        return;
    }

    // ---- W-GEMM tile role (bid < 128): output rows n0..n0+63, cols kc0..+127
    const uint32_t smb = smem_u32(smv);
    const int n0  = (bid >> 3) * 64;    // A-side (output WT row, contracts j)
    const int kc0 = (bid & 7) * 128;    // B-side (output WT col)

    const int lane = tid & 31;
    const int warp = tid >> 5;
    const int wm = warp >> 2;           // 0..1 (32 rows each)
    const int wn = warp & 3;            // 0..3 (32 cols each)
    const int l7  = lane & 7;
    const int lm  = lane & 15;
    const int hi4 = lane >> 4;

    float4 ra[4];   // A chunk: Wo[j0+jj][n0..+63], 64x64 fp32
    float4 rb[8];   // B chunk: Wv[kc0+kk][j0..+63], 128x64 fp32

    auto gload = [&](int t) {
        const int j0 = t * 64;
        #pragma unroll
        for (int i = 0; i < 4; i++) {
            int idx = i * 256 + tid;
            int jj = idx >> 4, nn = (idx & 15) * 4;
            ra[i] = *(const float4*)(Wo + (size_t)(j0 + jj) * DD + n0 + nn);
        }
        #pragma unroll
        for (int i = 0; i < 8; i++) {
            int idx = i * 256 + tid;
            int kk = idx >> 4, jj = (idx & 15) * 4;
            rb[i] = *(const float4*)(Wv + (size_t)(kc0 + kk) * DD + j0 + jj);
        }
    };
    auto gstore = [&](int buf) {
        const int base = buf * S1_STAGE;
        // A: transpose-convert; smem row = n (64 rows x 128B), halves along j
        #pragma unroll
        for (int i = 0; i < 4; i++) {
            int idx = i * 256 + tid;
            int jj = idx >> 4, nn = (idx & 15) * 4;
            float va[4] = { ra[i].x, ra[i].y, ra[i].z, ra[i].w };
            #pragma unroll
            for (int e = 0; e < 4; e++) {
                int row = nn + e;
                int off = base + row * 128 + (((jj >> 3) ^ (row & 7)) << 4) + (jj & 7) * 2;
                *(unsigned short*)(smv + off) = f2h(va[e]);
            }
        }
        // B: row-convert; smem row = k (128 rows x 128B), halves along j
        #pragma unroll
        for (int i = 0; i < 8; i++) {
            int idx = i * 256 + tid;
            int kk = idx >> 4, jj = (idx & 15) * 4;
            uint2 o = { pack_f16x2(rb[i].x, rb[i].y), pack_f16x2(rb[i].z, rb[i].w) };
            int off = base + 8192 + kk * 128 + (((jj >> 3) ^ (kk & 7)) << 4) + (jj & 7) * 2;
            *(uint2*)(smv + off) = o;   // (jj&7) in {0,4} -> byte {0,8}, 8B aligned
        }
    };

    float acc[2][4][4];
    #pragma unroll
    for (int mt = 0; mt < 2; mt++)
        #pragma unroll
        for (int nt = 0; nt < 4; nt++)
            #pragma unroll
            for (int i = 0; i < 4; i++)
                acc[mt][nt][i] = 0.f;

    gload(0);
    gstore(0);
    __syncthreads();

    const int NT = 16;
    for (int t = 0; t < NT; t++) {
        const int buf = t & 1;
        if (t + 1 < NT) gload(t + 1);   // global loads in flight during compute

        const uint32_t aB = smb + buf * S1_STAGE;
        const uint32_t bB = aB + 8192;
        #pragma unroll
        for (int ks = 0; ks < 4; ks++) {
            uint32_t a[2][4], b[4][2];
            #pragma unroll
            for (int mt = 0; mt < 2; mt++) {
                int m = wm * 32 + mt * 16 + lm;
                uint32_t ad = aB + m * 128 + ((((ks * 2 + hi4)) ^ l7) << 4);
                ldsm4(a[mt][0], a[mt][1], a[mt][2], a[mt][3], ad);
            }
            #pragma unroll
            for (int p = 0; p < 2; p++) {
                int im = lane >> 3;
                int nt = p * 2 + (im >> 1);
                int ch = (ks * 2 + (im & 1)) ^ l7;
                int n  = wn * 32 + nt * 8 + l7;
                uint32_t bd = bB + n * 128 + (ch << 4);
                ldsm4(b[p * 2][0], b[p * 2][1], b[p * 2 + 1][0], b[p * 2 + 1][1], bd);
            }
            #pragma unroll
            for (int mt = 0; mt < 2; mt++)
                #pragma unroll
                for (int nt = 0; nt < 4; nt++)
                    mma_f16(acc[mt][nt], a[mt], b[nt]);
        }
        __syncthreads();
        if (t + 1 < NT) {
            gstore((t + 1) & 1);
            __syncthreads();
        }
    }

    // Epilogue: WT rows = n, cols = k; write fp16 (x2048)
    #pragma unroll
    for (int mt = 0; mt < 2; mt++) {
        #pragma unroll
        for (int nt = 0; nt < 4; nt++) {
            const int row = n0 + wm * 32 + mt * 16 + (lane >> 2);
            const int col = kc0 + wn * 32 + nt * 8 + 2 * (lane & 3);
            float w0 = acc[mt][nt][0] * 2048.0f;
            float w1 = acc[mt][nt][1] * 2048.0f;
            float w2 = acc[mt][nt][2] * 2048.0f;
            float w3 = acc[mt][nt][3] * 2048.0f;
            *(uint32_t*)(wt + (size_t)row * DD + col)       = pack_f16x2(w0, w1);
            *(uint32_t*)(wt + (size_t)(row + 8) * DD + col) = pack_f16x2(w2, w3);
        }
    }
}

// ---------------------------------------------------------------------------
// Main fp16 GEMM: out[8192][1024] = xh @ WT^T + c, where the block reduces
// c[col] = bo[col] + 2048*sum_g bpart[g][col] into smem in its prologue
// (L2-hot, overlapped with the cp.async pipeline spin-up).
// BM=128, BN=128, 3-stage cp.async, xor-swizzled smem (validated mainloop).
// ---------------------------------------------------------------------------
#define MAIN_SMEM ((128 + 128) * 128 * 3)   // 98304

__global__ __launch_bounds__(256, 2)
void gemm_f16_main(const __half* __restrict__ A, const __half* __restrict__ B,
                   const float* __restrict__ bpart, const float* __restrict__ bo,
                   float* __restrict__ Cf) {
    constexpr int BM = 128;
    constexpr int MT = BM / 32;              // 4
    constexpr int STG = (BM + 128) * 128;
    extern __shared__ char smv[];
    __shared__ float c_sm[128];
    const uint32_t smb = smem_u32(smv);

    const int tid  = threadIdx.x;
    const int lane = tid & 31;
    const int warp = tid >> 5;
    const int wm = warp >> 2;
    const int wn = warp & 3;
    const int blockRow = blockIdx.y * BM;
    const int blockCol = blockIdx.x * 128;

    // Prologue: reduce bias for this block's 128 columns (before pipeline)
    if (tid < 128) {
        const int col = blockCol + tid;
        float s = bo[col];
        #pragma unroll
        for (int g = 0; g < 8; g++)
            s += 2048.0f * bpart[g * DD + col];
        c_sm[tid] = s;
    }

    const int l7  = lane & 7;
    const int lm  = lane & 15;
    const int hi4 = lane >> 4;

    auto issue = [&](int t, int buf) {
        const int k0 = t << 6;
        const uint32_t aB = smb + buf * STG;
        const uint32_t bB = aB + BM * 128;
        #pragma unroll
        for (int j = 0; j < BM / 32; j++) {
            int idx = j * 256 + tid;
            int row = idx >> 3, cc = idx & 7;
            uint32_t dst = aB + row * 128 + ((cc ^ (row & 7)) << 4);
            CP16(dst, A + (size_t)(blockRow + row) * DD + k0 + cc * 8);
        }
        #pragma unroll
        for (int j = 0; j < 4; j++) {
            int idx = j * 256 + tid;
            int row = idx >> 3, cc = idx & 7;
            uint32_t dst = bB + row * 128 + ((cc ^ (row & 7)) << 4);
            CP16(dst, B + (size_t)(blockCol + row) * DD + k0 + cc * 8);
        }
        CP_COMMIT();
    };

    float acc[MT][4][4];
    #pragma unroll
    for (int mt = 0; mt < MT; mt++)
        #pragma unroll
        for (int nt = 0; nt < 4; nt++)
            #pragma unroll
            for (int i = 0; i < 4; i++)
                acc[mt][nt][i] = 0.f;

    const int NT = 16;
    issue(0, 0);
    issue(1, 1);

    for (int t = 0; t < NT; t++) {
        const int buf = t % 3;
        if (t < NT - 1) CP_WAIT1(); else CP_WAIT0();
        __syncthreads();
        const uint32_t aB = smb + buf * STG;
        const uint32_t bB = aB + BM * 128;

        #pragma unroll
        for (int ks = 0; ks < 4; ks++) {
            uint32_t a[MT][4], b[4][2];
            #pragma unroll
            for (int mt = 0; mt < MT; mt++) {
                int m = wm * (BM / 2) + mt * 16 + lm;
                uint32_t ad = aB + m * 128 + ((((ks * 2 + hi4)) ^ l7) << 4);
                ldsm4(a[mt][0], a[mt][1], a[mt][2], a[mt][3], ad);
            }
            #pragma unroll
            for (int p = 0; p < 2; p++) {
                int im = lane >> 3;
                int nt = p * 2 + (im >> 1);
                int ch = (ks * 2 + (im & 1)) ^ l7;
                int n  = wn * 32 + nt * 8 + l7;
                uint32_t bd = bB + n * 128 + (ch << 4);
                ldsm4(b[p * 2][0], b[p * 2][1], b[p * 2 + 1][0], b[p * 2 + 1][1], bd);
            }
            #pragma unroll
            for (int mt = 0; mt < MT; mt++)
                #pragma unroll
                for (int nt = 0; nt < 4; nt++)
                    mma_f16(acc[mt][nt], a[mt], b[nt]);
        }
        if (t + 2 < NT) issue(t + 2, (t + 2) % 3);
    }

    #pragma unroll
    for (int mt = 0; mt < MT; mt++) {
        #pragma unroll
        for (int nt = 0; nt < 4; nt++) {
            const int row = blockRow + wm * (BM / 2) + mt * 16 + (lane >> 2);
            const int col = blockCol + wn * 32 + nt * 8 + 2 * (lane & 3);
            const int lc  = wn * 32 + nt * 8 + 2 * (lane & 3);
            float b0 = c_sm[lc], b1 = c_sm[lc + 1];
            float2 v0 = make_float2(acc[mt][nt][0] + b0, acc[mt][nt][1] + b1);
            float2 v1 = make_float2(acc[mt][nt][2] + b0, acc[mt][nt][3] + b1);
            *(float2*)(Cf + (size_t)row * DD + col)       = v0;
            *(float2*)(Cf + (size_t)(row + 8) * DD + col) = v1;
        }
    }
}

// ---------------------------------------------------------------------------
// Launch:  out = x @ (2048*Wv@Wo) + (2048*bv@Wo + bo)
// (encoder_x/Wq/bq/Wk/bk dead: softmax rows sum to 1; the reference einsum
// contracts both q and k, so scores contribute exactly L = 2048.)
// All-fp16 tensor path (measured rel_err 4.2e-4 < 1e-3). Two launches:
//   1) fused: W-GEMM (inline operand cvt) + x->fp16 + bias partials
//   2) main GEMM with in-block bias reduction prologue
// ---------------------------------------------------------------------------
extern "C" void kernel_launch(void* const* d_in, const int* in_sizes, int n_in,
                              void* d_out, int out_size) {
    const float* x  = (const float*)d_in[0];
    const float* Wv = (const float*)d_in[6];
    const float* bv = (const float*)d_in[7];
    const float* Wo = (const float*)d_in[8];
    const float* bo = (const float*)d_in[9];
    float* out = (float*)d_out;

    unsigned short *xh, *wt;
    float *bp;
    cudaGetSymbolAddress((void**)&xh, g_xh);
    cudaGetSymbolAddress((void**)&wt, g_wt);
    cudaGetSymbolAddress((void**)&bp, g_bpart);

    cudaFuncSetAttribute(stage1_kernel,
                         cudaFuncAttributeMaxDynamicSharedMemorySize, S1_SMEM);
    cudaFuncSetAttribute(gemm_f16_main,
                         cudaFuncAttributeMaxDynamicSharedMemorySize, MAIN_SMEM);

    // 1) fused: W-GEMM tiles + x->fp16 + bias partials
    stage1_kernel<<<S1_BLKS, 256, S1_SMEM>>>(Wo, Wv, bv, wt,
                                             (const float4*)x, (uint2*)xh, bp);

    // 2) out[8192][1024] = xh @ WT^T + (2048*sum(bpart) + bo)
    gemm_f16_main<<<dim3(8, 64), 256, MAIN_SMEM>>>(
        (const __half*)xh, (const __half*)wt, bp, bo, out);
}